// round 1
// baseline (speedup 1.0000x reference)
#include <cuda_runtime.h>
#include <math.h>

// ---------------- problem constants ----------------
#define BATCH   32
#define IMG     56          // H == W
#define C       384
#define WS      7
#define SSH     3           // shift
#define NH      12
#define HD      32
#define NTOK    49          // WS*WS
#define NWIN    64          // (56/7)^2
#define MROWS   (BATCH * IMG * IMG)       // 100352
#define TOKPI   (IMG * IMG)               // 3136
#define QKVC    (3 * C)                   // 1152
#define HIDDEN  (4 * C)                   // 1536

// ---------------- scratch (device globals; no allocations allowed) ----------------
static __device__ float g_hw  [(size_t)MROWS * C];       // LN1 windowed / LN2 out
static __device__ float g_qkv [(size_t)MROWS * QKVC];
static __device__ float g_att [(size_t)MROWS * C];       // attention output (window order)
static __device__ float g_x2  [(size_t)MROWS * C];       // residual after attention
static __device__ float g_fc1 [(size_t)MROWS * HIDDEN];

// ---------------- LayerNorm (+ optional shift/window gather) ----------------
// one block (128 thr) per output token; 384 = 3*128
__global__ void __launch_bounds__(128) ln_kernel(
    const float* __restrict__ x, const float* __restrict__ gamma,
    const float* __restrict__ beta, float* __restrict__ out, int gather)
{
    int t = blockIdx.x;
    int tid = threadIdx.x;
    int src;
    if (gather) {
        int b = t / TOKPI, r = t % TOKPI;
        int wh = r / (WS * IMG / WS * WS); // careful: layout below
        // window-token layout: t = ((b*8 + wh)*8 + ww)*49 + n
        int rr = r;
        wh = rr / 392; rr %= 392;
        int ww = rr / 49; int n = rr % 49;
        int i = n / 7, j = n % 7;
        int sr = (wh * 7 + i + SSH) % IMG;
        int sc = (ww * 7 + j + SSH) % IMG;
        src = b * TOKPI + sr * IMG + sc;
    } else {
        src = t;
    }
    const float* row = x + (size_t)src * C;
    float v0 = row[tid], v1 = row[tid + 128], v2 = row[tid + 256];
    float s  = v0 + v1 + v2;
    float sq = v0 * v0 + v1 * v1 + v2 * v2;
    #pragma unroll
    for (int o = 16; o > 0; o >>= 1) {
        s  += __shfl_down_sync(0xffffffffu, s,  o);
        sq += __shfl_down_sync(0xffffffffu, sq, o);
    }
    __shared__ float ws_[4], wq_[4];
    __shared__ float mu_s, rstd_s;
    int w = tid >> 5, l = tid & 31;
    if (l == 0) { ws_[w] = s; wq_[w] = sq; }
    __syncthreads();
    if (tid == 0) {
        float S = ws_[0] + ws_[1] + ws_[2] + ws_[3];
        float Q = wq_[0] + wq_[1] + wq_[2] + wq_[3];
        float mu = S * (1.0f / C);
        float var = Q * (1.0f / C) - mu * mu;
        mu_s = mu;
        rstd_s = rsqrtf(var + 1e-5f);
    }
    __syncthreads();
    float mu = mu_s, rs = rstd_s;
    float* orow = out + (size_t)t * C;
    orow[tid]       = (v0 - mu) * rs * gamma[tid]       + beta[tid];
    orow[tid + 128] = (v1 - mu) * rs * gamma[tid + 128] + beta[tid + 128];
    orow[tid + 256] = (v2 - mu) * rs * gamma[tid + 256] + beta[tid + 256];
}

// ---------------- SGEMM: out[M,N] = A[M,K] @ W[K,N] + bias, fused epilogues ----------------
#define EPI_NONE 0
#define EPI_GELU 1
#define EPI_PROJ 2   // window-reverse + roll scatter, + res[dest]
#define EPI_RES  3   // + res[row]

template<int EPI>
__global__ void __launch_bounds__(256) sgemm_kernel(
    const float* __restrict__ A, const float* __restrict__ W,
    const float* __restrict__ bias, float* __restrict__ out,
    const float* __restrict__ res, int NN, int KK)
{
    __shared__ float As[8][128];
    __shared__ float Bs[8][64];
    int tid = threadIdx.x;
    int tx = tid & 15;        // 16 col-groups * 4 = 64
    int ty = tid >> 4;        // 16 row-groups * 8 = 128
    int brow = blockIdx.y * 128;
    int bcol = blockIdx.x * 64;

    float acc[8][4];
    #pragma unroll
    for (int i = 0; i < 8; i++)
        #pragma unroll
        for (int j = 0; j < 4; j++) acc[i][j] = 0.f;

    int arow = tid >> 1;
    int ac   = (tid & 1) * 4;
    const float* Aptr = A + (size_t)(brow + arow) * KK + ac;
    int bl = tid >> 4, bc = (tid & 15) << 2;

    for (int k0 = 0; k0 < KK; k0 += 8) {
        float4 av = *(const float4*)(Aptr + k0);
        As[ac + 0][arow] = av.x;
        As[ac + 1][arow] = av.y;
        As[ac + 2][arow] = av.z;
        As[ac + 3][arow] = av.w;
        if (tid < 128) {
            *(float4*)&Bs[bl][bc] =
                *(const float4*)(W + (size_t)(k0 + bl) * NN + bcol + bc);
        }
        __syncthreads();
        #pragma unroll
        for (int k = 0; k < 8; k++) {
            float a[8], b[4];
            #pragma unroll
            for (int i = 0; i < 8; i++) a[i] = As[k][ty * 8 + i];
            #pragma unroll
            for (int j = 0; j < 4; j++) b[j] = Bs[k][tx * 4 + j];
            #pragma unroll
            for (int i = 0; i < 8; i++)
                #pragma unroll
                for (int j = 0; j < 4; j++)
                    acc[i][j] = fmaf(a[i], b[j], acc[i][j]);
        }
        __syncthreads();
    }

    #pragma unroll
    for (int i = 0; i < 8; i++) {
        int r = brow + ty * 8 + i;
        size_t orow;
        if (EPI == EPI_PROJ) {
            int b = r / TOKPI, rr = r % TOKPI;
            int wh = rr / 392; rr %= 392;
            int ww = rr / 49; int n = rr % 49;
            int ii = n / 7, jj = n % 7;
            int r0 = (wh * 7 + ii + SSH) % IMG;
            int c0 = (ww * 7 + jj + SSH) % IMG;
            orow = (size_t)(b * TOKPI + r0 * IMG + c0);
        } else {
            orow = (size_t)r;
        }
        #pragma unroll
        for (int j = 0; j < 4; j++) {
            int cc = bcol + tx * 4 + j;
            float v = acc[i][j] + bias[cc];
            if (EPI == EPI_GELU)
                v = 0.5f * v * (1.f + erff(v * 0.70710678118654752f));
            if (EPI == EPI_PROJ || EPI == EPI_RES)
                v += res[orow * NN + cc];
            out[orow * NN + cc] = v;
        }
    }
}

// ---------------- windowed attention: one block per (window, head) ----------------
__device__ __forceinline__ int regid(int r) { return r < (IMG - WS) ? 0 : (r < (IMG - SSH) ? 1 : 2); }

__global__ void __launch_bounds__(128) attn_kernel(
    const float* __restrict__ qkv, const float* __restrict__ bias_table,
    float* __restrict__ o)
{
    int h  = blockIdx.x;            // head
    int w  = blockIdx.y;            // global window
    int nw = w & 63;
    int wh = nw >> 3, ww = nw & 7;
    int tid = threadIdx.x;

    __shared__ float sq[49][32], sk[49][32], sv[49][32];
    __shared__ float ss[49][50];
    __shared__ float rsum[49];

    const float scale = 0.1767766952966369f;  // 1/sqrt(32)
    size_t base = (size_t)w * 49 * QKVC + h * HD;
    for (int idx = tid; idx < 49 * 32; idx += 128) {
        int n = idx >> 5, d = idx & 31;
        size_t rb = base + (size_t)n * QKVC + d;
        sq[n][d] = qkv[rb] * scale;
        sk[n][d] = qkv[rb + C];
        sv[n][d] = qkv[rb + 2 * C];
    }
    __syncthreads();

    for (int idx = tid; idx < 49 * 49; idx += 128) {
        int n = idx / 49, m = idx % 49;
        float dot = 0.f;
        #pragma unroll
        for (int d = 0; d < 32; d++) dot = fmaf(sq[n][d], sk[m][d], dot);
        int i1 = n / 7, j1 = n % 7, i2 = m / 7, j2 = m % 7;
        int ridx = (i1 - i2 + 6) * 13 + (j1 - j2 + 6);
        dot += bias_table[ridx * NH + h];
        int rn = regid(wh * 7 + i1) * 3 + regid(ww * 7 + j1);
        int rm = regid(wh * 7 + i2) * 3 + regid(ww * 7 + j2);
        if (rn != rm) dot -= 100.f;
        ss[n][m] = dot;
    }
    __syncthreads();

    if (tid < 49) {
        float mx = -1e30f;
        #pragma unroll 7
        for (int m = 0; m < 49; m++) mx = fmaxf(mx, ss[tid][m]);
        float sum = 0.f;
        #pragma unroll 7
        for (int m = 0; m < 49; m++) {
            float e = __expf(ss[tid][m] - mx);
            ss[tid][m] = e;
            sum += e;
        }
        rsum[tid] = 1.f / sum;
    }
    __syncthreads();

    for (int idx = tid; idx < 49 * 32; idx += 128) {
        int n = idx >> 5, d = idx & 31;
        float acc = 0.f;
        #pragma unroll 7
        for (int m = 0; m < 49; m++) acc = fmaf(ss[n][m], sv[m][d], acc);
        acc *= rsum[n];
        o[((size_t)w * 49 + n) * C + h * HD + d] = acc;
    }
}

// ---------------- launcher ----------------
extern "C" void kernel_launch(void* const* d_in, const int* in_sizes, int n_in,
                              void* d_out, int out_size)
{
    const float* x      = (const float*)d_in[0];
    const float* n1g    = (const float*)d_in[1];
    const float* n1b    = (const float*)d_in[2];
    const float* qkv_w  = (const float*)d_in[3];
    const float* qkv_b  = (const float*)d_in[4];
    const float* btab   = (const float*)d_in[5];
    const float* proj_w = (const float*)d_in[6];
    const float* proj_b = (const float*)d_in[7];
    const float* n2g    = (const float*)d_in[8];
    const float* n2b    = (const float*)d_in[9];
    const float* fc1_w  = (const float*)d_in[10];
    const float* fc1_b  = (const float*)d_in[11];
    const float* fc2_w  = (const float*)d_in[12];
    const float* fc2_b  = (const float*)d_in[13];
    float* out = (float*)d_out;

    float *hw, *qkv, *att, *x2, *fc1;
    cudaGetSymbolAddress((void**)&hw,  g_hw);
    cudaGetSymbolAddress((void**)&qkv, g_qkv);
    cudaGetSymbolAddress((void**)&att, g_att);
    cudaGetSymbolAddress((void**)&x2,  g_x2);
    cudaGetSymbolAddress((void**)&fc1, g_fc1);

    const int gy = MROWS / 128;  // 784

    // 1. LN1 + shift + window partition
    ln_kernel<<<MROWS, 128>>>(x, n1g, n1b, hw, 1);

    // 2. QKV GEMM: [M,384] @ [384,1152]
    sgemm_kernel<EPI_NONE><<<dim3(QKVC / 64, gy), 256>>>(hw, qkv_w, qkv_b, qkv, nullptr, QKVC, C);

    // 3. windowed attention
    attn_kernel<<<dim3(NH, BATCH * NWIN), 128>>>(qkv, btab, att);

    // 4. proj GEMM + window-reverse + roll + residual(x) -> x2
    sgemm_kernel<EPI_PROJ><<<dim3(C / 64, gy), 256>>>(att, proj_w, proj_b, x2, x, C, C);

    // 5. LN2
    ln_kernel<<<MROWS, 128>>>(x2, n2g, n2b, hw, 0);

    // 6. FC1 + exact GELU
    sgemm_kernel<EPI_GELU><<<dim3(HIDDEN / 64, gy), 256>>>(hw, fc1_w, fc1_b, fc1, nullptr, HIDDEN, C);

    // 7. FC2 + residual(x2) -> out
    sgemm_kernel<EPI_RES><<<dim3(C / 64, gy), 256>>>(fc1, fc2_w, fc2_b, out, x2, C, HIDDEN);
}

// round 2
// speedup vs baseline: 1.9141x; 1.9141x over previous
#include <cuda_runtime.h>
#include <math.h>
#include <stdint.h>

// ---------------- problem constants ----------------
#define BATCH   32
#define IMG     56
#define C       384
#define WS      7
#define SSH     3
#define NH      12
#define HD      32
#define NWIN    64
#define MROWS   (BATCH * IMG * IMG)       // 100352
#define TOKPI   (IMG * IMG)               // 3136
#define QKVC    (3 * C)                   // 1152
#define HIDDEN  (4 * C)                   // 1536

// ---------------- scratch ----------------
static __device__ float g_hw  [(size_t)MROWS * C];
static __device__ float g_qkv [(size_t)MROWS * QKVC];
static __device__ float g_att [(size_t)MROWS * C];
static __device__ float g_x2  [(size_t)MROWS * C];
static __device__ float g_fc1 [(size_t)MROWS * HIDDEN];

// ---------------- helpers ----------------
__device__ __forceinline__ uint32_t f2tf(float x) {
    uint32_t u;
    asm("cvt.rna.tf32.f32 %0, %1;" : "=r"(u) : "f"(x));
    return u;
}

__device__ __forceinline__ void mma_tf32(float c[4],
    uint32_t a0, uint32_t a1, uint32_t a2, uint32_t a3,
    uint32_t b0, uint32_t b1)
{
    asm volatile(
        "mma.sync.aligned.m16n8k8.row.col.f32.tf32.tf32.f32 "
        "{%0,%1,%2,%3},{%4,%5,%6,%7},{%8,%9},{%0,%1,%2,%3};"
        : "+f"(c[0]), "+f"(c[1]), "+f"(c[2]), "+f"(c[3])
        : "r"(a0), "r"(a1), "r"(a2), "r"(a3), "r"(b0), "r"(b1));
}

// ---------------- LayerNorm (+ optional shift/window gather) ----------------
__global__ void __launch_bounds__(128) ln_kernel(
    const float* __restrict__ x, const float* __restrict__ gamma,
    const float* __restrict__ beta, float* __restrict__ out, int gather)
{
    int t = blockIdx.x;
    int tid = threadIdx.x;
    int src;
    if (gather) {
        int b = t / TOKPI, rr = t % TOKPI;
        int wh = rr / 392; rr %= 392;
        int ww = rr / 49; int n = rr % 49;
        int i = n / 7, j = n % 7;
        int sr = (wh * 7 + i + SSH) % IMG;
        int sc = (ww * 7 + j + SSH) % IMG;
        src = b * TOKPI + sr * IMG + sc;
    } else {
        src = t;
    }
    const float* row = x + (size_t)src * C;
    float v0 = row[tid], v1 = row[tid + 128], v2 = row[tid + 256];
    float s  = v0 + v1 + v2;
    float sq = v0 * v0 + v1 * v1 + v2 * v2;
    #pragma unroll
    for (int o = 16; o > 0; o >>= 1) {
        s  += __shfl_down_sync(0xffffffffu, s,  o);
        sq += __shfl_down_sync(0xffffffffu, sq, o);
    }
    __shared__ float ws_[4], wq_[4];
    __shared__ float mu_s, rstd_s;
    int w = tid >> 5, l = tid & 31;
    if (l == 0) { ws_[w] = s; wq_[w] = sq; }
    __syncthreads();
    if (tid == 0) {
        float S = ws_[0] + ws_[1] + ws_[2] + ws_[3];
        float Q = wq_[0] + wq_[1] + wq_[2] + wq_[3];
        float mu = S * (1.0f / C);
        float var = Q * (1.0f / C) - mu * mu;
        mu_s = mu;
        rstd_s = rsqrtf(var + 1e-5f);
    }
    __syncthreads();
    float mu = mu_s, rs = rstd_s;
    float* orow = out + (size_t)t * C;
    orow[tid]       = (v0 - mu) * rs * gamma[tid]       + beta[tid];
    orow[tid + 128] = (v1 - mu) * rs * gamma[tid + 128] + beta[tid + 128];
    orow[tid + 256] = (v2 - mu) * rs * gamma[tid + 256] + beta[tid + 256];
}

// ---------------- TF32 tensor-core GEMM: out[M,N] = A[M,K] @ W[K,N] + bias ----------------
#define EPI_NONE 0
#define EPI_GELU 1
#define EPI_PROJ 2
#define EPI_RES  3

// block tile 128x128, K-step 16, 8 warps of 64x32 warp tiles
template<int EPI>
__global__ void __launch_bounds__(256, 2) mma_gemm(
    const float* __restrict__ A, const float* __restrict__ W,
    const float* __restrict__ bias, float* __restrict__ out,
    const float* __restrict__ res, int NN, int KK)
{
    __shared__ uint32_t As[16][136];   // [k][m], stride 136 -> banks 8t+g injective
    __shared__ uint32_t Bs[16][136];   // [k][n]

    int tid  = threadIdx.x;
    int lane = tid & 31, w = tid >> 5;
    int g = lane >> 2, t = lane & 3;
    int wm = (w >> 2) * 64;            // 0 or 64
    int wn = (w & 3) * 32;             // 0,32,64,96
    int brow = blockIdx.y * 128;
    int bcol = blockIdx.x * 128;

    float acc[4][4][4];
    #pragma unroll
    for (int mi = 0; mi < 4; mi++)
        #pragma unroll
        for (int ni = 0; ni < 4; ni++)
            #pragma unroll
            for (int q = 0; q < 4; q++) acc[mi][ni][q] = 0.f;

    // staging indices
    int am = tid >> 2;                 // 0..63 (A row within half-tile)
    int ac = (tid & 3) * 4;            // k offset 0,4,8,12
    int bk = tid >> 5;                 // 0..7
    int bn = (tid & 31) * 4;           // 0..124

    const float* Ap = A + (size_t)(brow + am) * KK + ac;
    const float* Wp = W + (size_t)bk * NN + bcol + bn;

    float4 pa0 = *(const float4*)(Ap);
    float4 pa1 = *(const float4*)(Ap + (size_t)64 * KK);
    float4 pb0 = *(const float4*)(Wp);
    float4 pb1 = *(const float4*)(Wp + (size_t)8 * NN);

    for (int k0 = 0; k0 < KK; k0 += 16) {
        // stage (with tf32 rounding)
        As[ac + 0][am] = f2tf(pa0.x);
        As[ac + 1][am] = f2tf(pa0.y);
        As[ac + 2][am] = f2tf(pa0.z);
        As[ac + 3][am] = f2tf(pa0.w);
        As[ac + 0][am + 64] = f2tf(pa1.x);
        As[ac + 1][am + 64] = f2tf(pa1.y);
        As[ac + 2][am + 64] = f2tf(pa1.z);
        As[ac + 3][am + 64] = f2tf(pa1.w);
        {
            uint4 v0 = { f2tf(pb0.x), f2tf(pb0.y), f2tf(pb0.z), f2tf(pb0.w) };
            uint4 v1 = { f2tf(pb1.x), f2tf(pb1.y), f2tf(pb1.z), f2tf(pb1.w) };
            *(uint4*)&Bs[bk][bn]     = v0;
            *(uint4*)&Bs[bk + 8][bn] = v1;
        }
        __syncthreads();

        if (k0 + 16 < KK) {
            pa0 = *(const float4*)(Ap + k0 + 16);
            pa1 = *(const float4*)(Ap + (size_t)64 * KK + k0 + 16);
            pb0 = *(const float4*)(Wp + (size_t)(k0 + 16) * NN);
            pb1 = *(const float4*)(Wp + (size_t)(k0 + 24) * NN);
        }

        #pragma unroll
        for (int ks = 0; ks < 2; ks++) {
            int kb = ks * 8;
            uint32_t af[4][4], bf[4][2];
            #pragma unroll
            for (int mi = 0; mi < 4; mi++) {
                int m0 = wm + mi * 16 + g;
                af[mi][0] = As[kb + t][m0];
                af[mi][1] = As[kb + t][m0 + 8];
                af[mi][2] = As[kb + t + 4][m0];
                af[mi][3] = As[kb + t + 4][m0 + 8];
            }
            #pragma unroll
            for (int ni = 0; ni < 4; ni++) {
                int n0 = wn + ni * 8 + g;
                bf[ni][0] = Bs[kb + t][n0];
                bf[ni][1] = Bs[kb + t + 4][n0];
            }
            #pragma unroll
            for (int mi = 0; mi < 4; mi++)
                #pragma unroll
                for (int ni = 0; ni < 4; ni++)
                    mma_tf32(acc[mi][ni], af[mi][0], af[mi][1], af[mi][2], af[mi][3],
                             bf[ni][0], bf[ni][1]);
        }
        __syncthreads();
    }

    // epilogue: c0,c1 -> (row g, cols 2t,2t+1); c2,c3 -> (row g+8)
    #pragma unroll
    for (int mi = 0; mi < 4; mi++) {
        int r0 = brow + wm + mi * 16 + g;
        int r1 = r0 + 8;
        size_t o0, o1;
        if (EPI == EPI_PROJ) {
            #pragma unroll
            for (int h = 0; h < 2; h++) {
                int r = h ? r1 : r0;
                int b = r / TOKPI, rr = r % TOKPI;
                int wh = rr / 392; rr %= 392;
                int ww = rr / 49; int n = rr % 49;
                int ii = n / 7, jj = n % 7;
                int sr = (wh * 7 + ii + SSH) % IMG;
                int sc = (ww * 7 + jj + SSH) % IMG;
                size_t v = (size_t)(b * TOKPI + sr * IMG + sc);
                if (h) o1 = v; else o0 = v;
            }
        } else {
            o0 = (size_t)r0; o1 = (size_t)r1;
        }
        #pragma unroll
        for (int ni = 0; ni < 4; ni++) {
            int c = bcol + wn + ni * 8 + 2 * t;
            float blo = bias[c], bhi = bias[c + 1];
            float v00 = acc[mi][ni][0] + blo;
            float v01 = acc[mi][ni][1] + bhi;
            float v10 = acc[mi][ni][2] + blo;
            float v11 = acc[mi][ni][3] + bhi;
            if (EPI == EPI_GELU) {
                v00 = 0.5f * v00 * (1.f + erff(v00 * 0.70710678118654752f));
                v01 = 0.5f * v01 * (1.f + erff(v01 * 0.70710678118654752f));
                v10 = 0.5f * v10 * (1.f + erff(v10 * 0.70710678118654752f));
                v11 = 0.5f * v11 * (1.f + erff(v11 * 0.70710678118654752f));
            }
            if (EPI == EPI_PROJ || EPI == EPI_RES) {
                v00 += res[o0 * NN + c];
                v01 += res[o0 * NN + c + 1];
                v10 += res[o1 * NN + c];
                v11 += res[o1 * NN + c + 1];
            }
            float2 lo = { v00, v01 };
            float2 hi = { v10, v11 };
            *(float2*)&out[o0 * NN + c] = lo;
            *(float2*)&out[o1 * NN + c] = hi;
        }
    }
}

// ---------------- windowed attention ----------------
__device__ __forceinline__ int regid(int r) { return r < (IMG - WS) ? 0 : (r < (IMG - SSH) ? 1 : 2); }

__global__ void __launch_bounds__(128) attn_kernel(
    const float* __restrict__ qkv, const float* __restrict__ bias_table,
    float* __restrict__ o)
{
    int h  = blockIdx.x;
    int w  = blockIdx.y;
    int nw = w & 63;
    int wh = nw >> 3, ww = nw & 7;
    int tid = threadIdx.x;

    __shared__ float sq[49][32], sk[49][32], sv[49][32];
    __shared__ float ss[49][50];
    __shared__ float rsum[49];

    const float scale = 0.1767766952966369f;
    size_t base = (size_t)w * 49 * QKVC + h * HD;
    for (int idx = tid; idx < 49 * 32; idx += 128) {
        int n = idx >> 5, d = idx & 31;
        size_t rb = base + (size_t)n * QKVC + d;
        sq[n][d] = qkv[rb] * scale;
        sk[n][d] = qkv[rb + C];
        sv[n][d] = qkv[rb + 2 * C];
    }
    __syncthreads();

    for (int idx = tid; idx < 49 * 49; idx += 128) {
        int n = idx / 49, m = idx % 49;
        float dot = 0.f;
        #pragma unroll
        for (int d = 0; d < 32; d++) dot = fmaf(sq[n][d], sk[m][d], dot);
        int i1 = n / 7, j1 = n % 7, i2 = m / 7, j2 = m % 7;
        int ridx = (i1 - i2 + 6) * 13 + (j1 - j2 + 6);
        dot += bias_table[ridx * NH + h];
        int rn = regid(wh * 7 + i1) * 3 + regid(ww * 7 + j1);
        int rm = regid(wh * 7 + i2) * 3 + regid(ww * 7 + j2);
        if (rn != rm) dot -= 100.f;
        ss[n][m] = dot;
    }
    __syncthreads();

    if (tid < 49) {
        float mx = -1e30f;
        #pragma unroll 7
        for (int m = 0; m < 49; m++) mx = fmaxf(mx, ss[tid][m]);
        float sum = 0.f;
        #pragma unroll 7
        for (int m = 0; m < 49; m++) {
            float e = __expf(ss[tid][m] - mx);
            ss[tid][m] = e;
            sum += e;
        }
        rsum[tid] = 1.f / sum;
    }
    __syncthreads();

    for (int idx = tid; idx < 49 * 32; idx += 128) {
        int n = idx >> 5, d = idx & 31;
        float acc = 0.f;
        #pragma unroll 7
        for (int m = 0; m < 49; m++) acc = fmaf(ss[n][m], sv[m][d], acc);
        acc *= rsum[n];
        o[((size_t)w * 49 + n) * C + h * HD + d] = acc;
    }
}

// ---------------- launcher ----------------
extern "C" void kernel_launch(void* const* d_in, const int* in_sizes, int n_in,
                              void* d_out, int out_size)
{
    const float* x      = (const float*)d_in[0];
    const float* n1g    = (const float*)d_in[1];
    const float* n1b    = (const float*)d_in[2];
    const float* qkv_w  = (const float*)d_in[3];
    const float* qkv_b  = (const float*)d_in[4];
    const float* btab   = (const float*)d_in[5];
    const float* proj_w = (const float*)d_in[6];
    const float* proj_b = (const float*)d_in[7];
    const float* n2g    = (const float*)d_in[8];
    const float* n2b    = (const float*)d_in[9];
    const float* fc1_w  = (const float*)d_in[10];
    const float* fc1_b  = (const float*)d_in[11];
    const float* fc2_w  = (const float*)d_in[12];
    const float* fc2_b  = (const float*)d_in[13];
    float* out = (float*)d_out;

    float *hw, *qkv, *att, *x2, *fc1;
    cudaGetSymbolAddress((void**)&hw,  g_hw);
    cudaGetSymbolAddress((void**)&qkv, g_qkv);
    cudaGetSymbolAddress((void**)&att, g_att);
    cudaGetSymbolAddress((void**)&x2,  g_x2);
    cudaGetSymbolAddress((void**)&fc1, g_fc1);

    const int gy = MROWS / 128;  // 784

    // 1. LN1 + shift + window partition
    ln_kernel<<<MROWS, 128>>>(x, n1g, n1b, hw, 1);

    // 2. QKV GEMM: [M,384] @ [384,1152]
    mma_gemm<EPI_NONE><<<dim3(QKVC / 128, gy), 256>>>(hw, qkv_w, qkv_b, qkv, nullptr, QKVC, C);

    // 3. windowed attention
    attn_kernel<<<dim3(NH, BATCH * NWIN), 128>>>(qkv, btab, att);

    // 4. proj GEMM + window-reverse + roll + residual(x) -> x2
    mma_gemm<EPI_PROJ><<<dim3(C / 128, gy), 256>>>(att, proj_w, proj_b, x2, x, C, C);

    // 5. LN2
    ln_kernel<<<MROWS, 128>>>(x2, n2g, n2b, hw, 0);

    // 6. FC1 + exact GELU
    mma_gemm<EPI_GELU><<<dim3(HIDDEN / 128, gy), 256>>>(hw, fc1_w, fc1_b, fc1, nullptr, HIDDEN, C);

    // 7. FC2 + residual(x2) -> out
    mma_gemm<EPI_RES><<<dim3(C / 128, gy), 256>>>(fc1, fc2_w, fc2_b, out, x2, C, HIDDEN);
}

// round 3
// speedup vs baseline: 2.2432x; 1.1720x over previous
#include <cuda_runtime.h>
#include <math.h>
#include <stdint.h>

// ---------------- problem constants ----------------
#define BATCH   32
#define IMG     56
#define C       384
#define WS      7
#define SSH     3
#define NH      12
#define HD      32
#define NWIN    64
#define MROWS   (BATCH * IMG * IMG)       // 100352
#define TOKPI   (IMG * IMG)               // 3136
#define QKVC    (3 * C)                   // 1152
#define HIDDEN  (4 * C)                   // 1536

#define STAGES  4
#define APAD    20                        // A row stride (floats): (20g+t)%32 injective
#define BPAD    136                       // B row stride (floats): (8t+g)%32 injective
#define A_STAGE (128 * APAD)              // floats per A stage
#define B_STAGE (16 * BPAD)               // floats per B stage
#define SMEM_BYTES (STAGES * (A_STAGE + B_STAGE) * 4)   // 75776

// ---------------- scratch ----------------
static __device__ float g_hw  [(size_t)MROWS * C];
static __device__ float g_qkv [(size_t)MROWS * QKVC];
static __device__ float g_att [(size_t)MROWS * C];
static __device__ float g_x2  [(size_t)MROWS * C];
static __device__ float g_fc1 [(size_t)MROWS * HIDDEN];

// ---------------- helpers ----------------
__device__ __forceinline__ void cp16(float* dst, const float* src) {
    uint32_t d = (uint32_t)__cvta_generic_to_shared(dst);
    asm volatile("cp.async.cg.shared.global [%0], [%1], 16;\n" :: "r"(d), "l"(src));
}
__device__ __forceinline__ void cp_commit() {
    asm volatile("cp.async.commit_group;\n" ::);
}
template<int N>
__device__ __forceinline__ void cp_wait() {
    asm volatile("cp.async.wait_group %0;\n" :: "n"(N));
}

__device__ __forceinline__ void mma_tf32(float c[4],
    uint32_t a0, uint32_t a1, uint32_t a2, uint32_t a3,
    uint32_t b0, uint32_t b1)
{
    asm volatile(
        "mma.sync.aligned.m16n8k8.row.col.f32.tf32.tf32.f32 "
        "{%0,%1,%2,%3},{%4,%5,%6,%7},{%8,%9},{%0,%1,%2,%3};"
        : "+f"(c[0]), "+f"(c[1]), "+f"(c[2]), "+f"(c[3])
        : "r"(a0), "r"(a1), "r"(a2), "r"(a3), "r"(b0), "r"(b1));
}

// ---------------- LayerNorm (+ optional shift/window gather) ----------------
__global__ void __launch_bounds__(128) ln_kernel(
    const float* __restrict__ x, const float* __restrict__ gamma,
    const float* __restrict__ beta, float* __restrict__ out, int gather)
{
    int t = blockIdx.x;
    int tid = threadIdx.x;
    int src;
    if (gather) {
        int b = t / TOKPI, rr = t % TOKPI;
        int wh = rr / 392; rr %= 392;
        int ww = rr / 49; int n = rr % 49;
        int i = n / 7, j = n % 7;
        int sr = (wh * 7 + i + SSH) % IMG;
        int sc = (ww * 7 + j + SSH) % IMG;
        src = b * TOKPI + sr * IMG + sc;
    } else {
        src = t;
    }
    const float* row = x + (size_t)src * C;
    float v0 = row[tid], v1 = row[tid + 128], v2 = row[tid + 256];
    float s  = v0 + v1 + v2;
    float sq = v0 * v0 + v1 * v1 + v2 * v2;
    #pragma unroll
    for (int o = 16; o > 0; o >>= 1) {
        s  += __shfl_down_sync(0xffffffffu, s,  o);
        sq += __shfl_down_sync(0xffffffffu, sq, o);
    }
    __shared__ float ws_[4], wq_[4];
    __shared__ float mu_s, rstd_s;
    int w = tid >> 5, l = tid & 31;
    if (l == 0) { ws_[w] = s; wq_[w] = sq; }
    __syncthreads();
    if (tid == 0) {
        float S = ws_[0] + ws_[1] + ws_[2] + ws_[3];
        float Q = wq_[0] + wq_[1] + wq_[2] + wq_[3];
        float mu = S * (1.0f / C);
        float var = Q * (1.0f / C) - mu * mu;
        mu_s = mu;
        rstd_s = rsqrtf(var + 1e-5f);
    }
    __syncthreads();
    float mu = mu_s, rs = rstd_s;
    float* orow = out + (size_t)t * C;
    orow[tid]       = (v0 - mu) * rs * gamma[tid]       + beta[tid];
    orow[tid + 128] = (v1 - mu) * rs * gamma[tid + 128] + beta[tid + 128];
    orow[tid + 256] = (v2 - mu) * rs * gamma[tid + 256] + beta[tid + 256];
}

// ---------------- TF32 tensor-core GEMM, cp.async 4-stage pipeline ----------------
#define EPI_NONE 0
#define EPI_GELU 1
#define EPI_PROJ 2
#define EPI_RES  3

template<int EPI>
__global__ void __launch_bounds__(256, 2) mma_gemm(
    const float* __restrict__ A, const float* __restrict__ W,
    const float* __restrict__ bias, float* __restrict__ out,
    const float* __restrict__ res, int NN, int KK)
{
    extern __shared__ float smem[];
    float* AsBase = smem;                       // [STAGES][128][APAD]
    float* BsBase = smem + STAGES * A_STAGE;    // [STAGES][16][BPAD]

    int tid  = threadIdx.x;
    int lane = tid & 31, w = tid >> 5;
    int g = lane >> 2, t = lane & 3;
    int wm = (w >> 2) * 64;
    int wn = (w & 3) * 32;
    int brow = blockIdx.y * 128;
    int bcol = blockIdx.x * 128;

    float acc[4][4][4];
    #pragma unroll
    for (int mi = 0; mi < 4; mi++)
        #pragma unroll
        for (int ni = 0; ni < 4; ni++)
            #pragma unroll
            for (int q = 0; q < 4; q++) acc[mi][ni][q] = 0.f;

    // staging: A = 512 chunks of 16B (row = c>>2, k4 = (c&3)*4)
    //          B = 512 chunks of 16B (krow = c>>5, n4 = (c&31)*4)
    int ar0 = tid >> 2,          ak0 = (tid & 3) * 4;     // chunk tid
    int ar1 = (tid + 256) >> 2,  ak1 = (tid & 3) * 4;     // chunk tid+256
    int bk0 = tid >> 5,          bn0 = (tid & 31) * 4;
    int bk1 = (tid >> 5) + 8,    bn1 = (tid & 31) * 4;

    const float* Ag0 = A + (size_t)(brow + ar0) * KK + ak0;
    const float* Ag1 = A + (size_t)(brow + ar1) * KK + ak1;
    const float* Bg0 = W + (size_t)bk0 * NN + bcol + bn0;
    const float* Bg1 = W + (size_t)bk1 * NN + bcol + bn1;

    const int kt = KK >> 4;   // K16 iterations

    // prologue: fill STAGES-1 stages
    #pragma unroll
    for (int s = 0; s < STAGES - 1; s++) {
        int k0 = s << 4;
        float* As = AsBase + s * A_STAGE;
        float* Bs = BsBase + s * B_STAGE;
        cp16(As + ar0 * APAD + ak0, Ag0 + k0);
        cp16(As + ar1 * APAD + ak1, Ag1 + k0);
        cp16(Bs + bk0 * BPAD + bn0, Bg0 + (size_t)k0 * NN);
        cp16(Bs + bk1 * BPAD + bn1, Bg1 + (size_t)k0 * NN);
        cp_commit();
    }

    for (int it = 0; it < kt; it++) {
        int s = it & (STAGES - 1);
        cp_wait<STAGES - 2>();
        __syncthreads();

        // prefetch stage it+STAGES-1
        int pf = it + STAGES - 1;
        if (pf < kt) {
            int ps = pf & (STAGES - 1);
            int k0 = pf << 4;
            float* As = AsBase + ps * A_STAGE;
            float* Bs = BsBase + ps * B_STAGE;
            cp16(As + ar0 * APAD + ak0, Ag0 + k0);
            cp16(As + ar1 * APAD + ak1, Ag1 + k0);
            cp16(Bs + bk0 * BPAD + bn0, Bg0 + (size_t)k0 * NN);
            cp16(Bs + bk1 * BPAD + bn1, Bg1 + (size_t)k0 * NN);
        }
        cp_commit();

        const float* As = AsBase + s * A_STAGE;
        const float* Bs = BsBase + s * B_STAGE;

        #pragma unroll
        for (int ks = 0; ks < 2; ks++) {
            int kb = ks * 8;
            uint32_t af[4][4], bf[4][2];
            #pragma unroll
            for (int mi = 0; mi < 4; mi++) {
                int m0 = wm + mi * 16 + g;
                af[mi][0] = __float_as_uint(As[(m0)     * APAD + kb + t]);
                af[mi][1] = __float_as_uint(As[(m0 + 8) * APAD + kb + t]);
                af[mi][2] = __float_as_uint(As[(m0)     * APAD + kb + t + 4]);
                af[mi][3] = __float_as_uint(As[(m0 + 8) * APAD + kb + t + 4]);
            }
            #pragma unroll
            for (int ni = 0; ni < 4; ni++) {
                int n0 = wn + ni * 8 + g;
                bf[ni][0] = __float_as_uint(Bs[(kb + t)     * BPAD + n0]);
                bf[ni][1] = __float_as_uint(Bs[(kb + t + 4) * BPAD + n0]);
            }
            #pragma unroll
            for (int mi = 0; mi < 4; mi++)
                #pragma unroll
                for (int ni = 0; ni < 4; ni++)
                    mma_tf32(acc[mi][ni], af[mi][0], af[mi][1], af[mi][2], af[mi][3],
                             bf[ni][0], bf[ni][1]);
        }
    }

    // epilogue
    #pragma unroll
    for (int mi = 0; mi < 4; mi++) {
        int r0 = brow + wm + mi * 16 + g;
        int r1 = r0 + 8;
        size_t o0, o1;
        if (EPI == EPI_PROJ) {
            #pragma unroll
            for (int h = 0; h < 2; h++) {
                int r = h ? r1 : r0;
                int b = r / TOKPI, rr = r % TOKPI;
                int wh = rr / 392; rr %= 392;
                int ww = rr / 49; int n = rr % 49;
                int ii = n / 7, jj = n % 7;
                int sr = (wh * 7 + ii + SSH) % IMG;
                int sc = (ww * 7 + jj + SSH) % IMG;
                size_t v = (size_t)(b * TOKPI + sr * IMG + sc);
                if (h) o1 = v; else o0 = v;
            }
        } else {
            o0 = (size_t)r0; o1 = (size_t)r1;
        }
        #pragma unroll
        for (int ni = 0; ni < 4; ni++) {
            int c = bcol + wn + ni * 8 + 2 * t;
            float blo = bias[c], bhi = bias[c + 1];
            float v00 = acc[mi][ni][0] + blo;
            float v01 = acc[mi][ni][1] + bhi;
            float v10 = acc[mi][ni][2] + blo;
            float v11 = acc[mi][ni][3] + bhi;
            if (EPI == EPI_GELU) {
                v00 = 0.5f * v00 * (1.f + erff(v00 * 0.70710678118654752f));
                v01 = 0.5f * v01 * (1.f + erff(v01 * 0.70710678118654752f));
                v10 = 0.5f * v10 * (1.f + erff(v10 * 0.70710678118654752f));
                v11 = 0.5f * v11 * (1.f + erff(v11 * 0.70710678118654752f));
            }
            if (EPI == EPI_PROJ || EPI == EPI_RES) {
                v00 += res[o0 * NN + c];
                v01 += res[o0 * NN + c + 1];
                v10 += res[o1 * NN + c];
                v11 += res[o1 * NN + c + 1];
            }
            float2 lo = { v00, v01 };
            float2 hi = { v10, v11 };
            *(float2*)&out[o0 * NN + c] = lo;
            *(float2*)&out[o1 * NN + c] = hi;
        }
    }
}

// ---------------- windowed attention ----------------
__device__ __forceinline__ int regid(int r) { return r < (IMG - WS) ? 0 : (r < (IMG - SSH) ? 1 : 2); }

__global__ void __launch_bounds__(128) attn_kernel(
    const float* __restrict__ qkv, const float* __restrict__ bias_table,
    float* __restrict__ o)
{
    int h  = blockIdx.x;
    int w  = blockIdx.y;
    int nw = w & 63;
    int wh = nw >> 3, ww = nw & 7;
    int tid = threadIdx.x;

    __shared__ float sq[49][32], sk[49][32], sv[49][32];
    __shared__ float ss[49][50];
    __shared__ float rsum[49];

    const float scale = 0.1767766952966369f;
    size_t base = (size_t)w * 49 * QKVC + h * HD;
    for (int idx = tid; idx < 49 * 32; idx += 128) {
        int n = idx >> 5, d = idx & 31;
        size_t rb = base + (size_t)n * QKVC + d;
        sq[n][d] = qkv[rb] * scale;
        sk[n][d] = qkv[rb + C];
        sv[n][d] = qkv[rb + 2 * C];
    }
    __syncthreads();

    for (int idx = tid; idx < 49 * 49; idx += 128) {
        int n = idx / 49, m = idx % 49;
        float dot = 0.f;
        #pragma unroll
        for (int d = 0; d < 32; d++) dot = fmaf(sq[n][d], sk[m][d], dot);
        int i1 = n / 7, j1 = n % 7, i2 = m / 7, j2 = m % 7;
        int ridx = (i1 - i2 + 6) * 13 + (j1 - j2 + 6);
        dot += bias_table[ridx * NH + h];
        int rn = regid(wh * 7 + i1) * 3 + regid(ww * 7 + j1);
        int rm = regid(wh * 7 + i2) * 3 + regid(ww * 7 + j2);
        if (rn != rm) dot -= 100.f;
        ss[n][m] = dot;
    }
    __syncthreads();

    if (tid < 49) {
        float mx = -1e30f;
        #pragma unroll 7
        for (int m = 0; m < 49; m++) mx = fmaxf(mx, ss[tid][m]);
        float sum = 0.f;
        #pragma unroll 7
        for (int m = 0; m < 49; m++) {
            float e = __expf(ss[tid][m] - mx);
            ss[tid][m] = e;
            sum += e;
        }
        rsum[tid] = 1.f / sum;
    }
    __syncthreads();

    for (int idx = tid; idx < 49 * 32; idx += 128) {
        int n = idx >> 5, d = idx & 31;
        float acc = 0.f;
        #pragma unroll 7
        for (int m = 0; m < 49; m++) acc = fmaf(ss[n][m], sv[m][d], acc);
        acc *= rsum[n];
        o[((size_t)w * 49 + n) * C + h * HD + d] = acc;
    }
}

// ---------------- launcher ----------------
extern "C" void kernel_launch(void* const* d_in, const int* in_sizes, int n_in,
                              void* d_out, int out_size)
{
    const float* x      = (const float*)d_in[0];
    const float* n1g    = (const float*)d_in[1];
    const float* n1b    = (const float*)d_in[2];
    const float* qkv_w  = (const float*)d_in[3];
    const float* qkv_b  = (const float*)d_in[4];
    const float* btab   = (const float*)d_in[5];
    const float* proj_w = (const float*)d_in[6];
    const float* proj_b = (const float*)d_in[7];
    const float* n2g    = (const float*)d_in[8];
    const float* n2b    = (const float*)d_in[9];
    const float* fc1_w  = (const float*)d_in[10];
    const float* fc1_b  = (const float*)d_in[11];
    const float* fc2_w  = (const float*)d_in[12];
    const float* fc2_b  = (const float*)d_in[13];
    float* out = (float*)d_out;

    float *hw, *qkv, *att, *x2, *fc1;
    cudaGetSymbolAddress((void**)&hw,  g_hw);
    cudaGetSymbolAddress((void**)&qkv, g_qkv);
    cudaGetSymbolAddress((void**)&att, g_att);
    cudaGetSymbolAddress((void**)&x2,  g_x2);
    cudaGetSymbolAddress((void**)&fc1, g_fc1);

    static int smem_set = 0;
    if (!smem_set) {
        cudaFuncSetAttribute(mma_gemm<EPI_NONE>, cudaFuncAttributeMaxDynamicSharedMemorySize, SMEM_BYTES);
        cudaFuncSetAttribute(mma_gemm<EPI_GELU>, cudaFuncAttributeMaxDynamicSharedMemorySize, SMEM_BYTES);
        cudaFuncSetAttribute(mma_gemm<EPI_PROJ>, cudaFuncAttributeMaxDynamicSharedMemorySize, SMEM_BYTES);
        cudaFuncSetAttribute(mma_gemm<EPI_RES>,  cudaFuncAttributeMaxDynamicSharedMemorySize, SMEM_BYTES);
        smem_set = 1;
    }

    const int gy = MROWS / 128;  // 784

    // 1. LN1 + shift + window partition
    ln_kernel<<<MROWS, 128>>>(x, n1g, n1b, hw, 1);

    // 2. QKV GEMM
    mma_gemm<EPI_NONE><<<dim3(QKVC / 128, gy), 256, SMEM_BYTES>>>(hw, qkv_w, qkv_b, qkv, nullptr, QKVC, C);

    // 3. windowed attention
    attn_kernel<<<dim3(NH, BATCH * NWIN), 128>>>(qkv, btab, att);

    // 4. proj GEMM + scatter + residual
    mma_gemm<EPI_PROJ><<<dim3(C / 128, gy), 256, SMEM_BYTES>>>(att, proj_w, proj_b, x2, x, C, C);

    // 5. LN2
    ln_kernel<<<MROWS, 128>>>(x2, n2g, n2b, hw, 0);

    // 6. FC1 + GELU
    mma_gemm<EPI_GELU><<<dim3(HIDDEN / 128, gy), 256, SMEM_BYTES>>>(hw, fc1_w, fc1_b, fc1, nullptr, HIDDEN, C);

    // 7. FC2 + residual
    mma_gemm<EPI_RES><<<dim3(C / 128, gy), 256, SMEM_BYTES>>>(fc1, fc2_w, fc2_b, out, x2, C, HIDDEN);
}

// round 4
// speedup vs baseline: 3.1833x; 1.4191x over previous
#include <cuda_runtime.h>
#include <math.h>
#include <stdint.h>

// ---------------- problem constants ----------------
#define BATCH   32
#define IMG     56
#define C       384
#define WS      7
#define SSH     3
#define NH      12
#define HD      32
#define NWIN    64
#define MROWS   (BATCH * IMG * IMG)       // 100352
#define TOKPI   (IMG * IMG)               // 3136
#define QKVC    (3 * C)                   // 1152
#define HIDDEN  (4 * C)                   // 1536

#define STAGES  3
#define APAD    36                        // A row stride (floats), k32 tile: bank (4g+t) injective
#define BPAD    136                       // B row stride (floats): bank (8t+g) injective
#define A_STAGE (128 * APAD)              // 4608 floats
#define B_STAGE (32 * BPAD)               // 4352 floats
#define SMEM_BYTES (STAGES * (A_STAGE + B_STAGE) * 4)   // 107520

// ---------------- scratch ----------------
static __device__ float g_hw  [(size_t)MROWS * C];
static __device__ float g_qkv [(size_t)MROWS * QKVC];
static __device__ float g_att [(size_t)MROWS * C];
static __device__ float g_x2  [(size_t)MROWS * C];
static __device__ float g_fc1 [(size_t)MROWS * HIDDEN];

// ---------------- helpers ----------------
__device__ __forceinline__ void cp16(float* dst, const float* src) {
    uint32_t d = (uint32_t)__cvta_generic_to_shared(dst);
    asm volatile("cp.async.cg.shared.global [%0], [%1], 16;\n" :: "r"(d), "l"(src));
}
__device__ __forceinline__ void cp_commit() {
    asm volatile("cp.async.commit_group;\n" ::);
}
template<int N>
__device__ __forceinline__ void cp_wait() {
    asm volatile("cp.async.wait_group %0;\n" :: "n"(N));
}

__device__ __forceinline__ void mma_tf32(float c[4],
    uint32_t a0, uint32_t a1, uint32_t a2, uint32_t a3,
    uint32_t b0, uint32_t b1)
{
    asm volatile(
        "mma.sync.aligned.m16n8k8.row.col.f32.tf32.tf32.f32 "
        "{%0,%1,%2,%3},{%4,%5,%6,%7},{%8,%9},{%0,%1,%2,%3};"
        : "+f"(c[0]), "+f"(c[1]), "+f"(c[2]), "+f"(c[3])
        : "r"(a0), "r"(a1), "r"(a2), "r"(a3), "r"(b0), "r"(b1));
}

// ---------------- LayerNorm: warp-per-token (+ optional shift/window gather) ----------------
__global__ void __launch_bounds__(256) ln_kernel(
    const float* __restrict__ x, const float* __restrict__ gamma,
    const float* __restrict__ beta, float* __restrict__ out, int gather)
{
    int warp = threadIdx.x >> 5, lane = threadIdx.x & 31;
    int t = blockIdx.x * 8 + warp;
    if (t >= MROWS) return;
    int src;
    if (gather) {
        int b = t / TOKPI, rr = t % TOKPI;
        int wh = rr / 392; rr %= 392;
        int ww = rr / 49; int n = rr % 49;
        int i = n / 7, j = n % 7;
        int sr = (wh * 7 + i + SSH) % IMG;
        int sc = (ww * 7 + j + SSH) % IMG;
        src = b * TOKPI + sr * IMG + sc;
    } else {
        src = t;
    }
    const float* row = x + (size_t)src * C;
    float v[12];
    float s = 0.f, sq = 0.f;
    #pragma unroll
    for (int j = 0; j < 12; j++) {
        v[j] = row[lane + 32 * j];
        s += v[j];
        sq += v[j] * v[j];
    }
    #pragma unroll
    for (int o = 16; o > 0; o >>= 1) {
        s  += __shfl_xor_sync(0xffffffffu, s,  o);
        sq += __shfl_xor_sync(0xffffffffu, sq, o);
    }
    float mu = s * (1.0f / C);
    float var = sq * (1.0f / C) - mu * mu;
    float rs = rsqrtf(var + 1e-5f);
    float* orow = out + (size_t)t * C;
    #pragma unroll
    for (int j = 0; j < 12; j++) {
        int c = lane + 32 * j;
        orow[c] = (v[j] - mu) * rs * gamma[c] + beta[c];
    }
}

// ---------------- TF32 tensor-core GEMM, cp.async 3-stage pipeline, K-step 32 ----------------
#define EPI_NONE 0
#define EPI_GELU 1
#define EPI_PROJ 2
#define EPI_RES  3

template<int EPI>
__global__ void __launch_bounds__(256, 2) mma_gemm(
    const float* __restrict__ A, const float* __restrict__ W,
    const float* __restrict__ bias, float* __restrict__ out,
    const float* __restrict__ res, int NN, int KK)
{
    extern __shared__ float smem[];
    float* AsBase = smem;                       // [STAGES][128][APAD]
    float* BsBase = smem + STAGES * A_STAGE;    // [STAGES][32][BPAD]

    int tid  = threadIdx.x;
    int lane = tid & 31, w = tid >> 5;
    int g = lane >> 2, t = lane & 3;
    int wm = (w >> 2) * 64;
    int wn = (w & 3) * 32;
    int brow = blockIdx.y * 128;
    int bcol = blockIdx.x * 128;

    float acc[4][4][4];
    #pragma unroll
    for (int mi = 0; mi < 4; mi++)
        #pragma unroll
        for (int ni = 0; ni < 4; ni++)
            #pragma unroll
            for (int q = 0; q < 4; q++) acc[mi][ni][q] = 0.f;

    // staging: A tile 128x32 = 1024 16B-chunks; B tile 32x128 = 1024 chunks
    int ar = tid >> 3, ak = (tid & 7) * 4;     // A: rows ar+32i, k col ak
    int bk = tid >> 5, bn = (tid & 31) * 4;    // B: rows bk+8i,  n col bn

    const float* Ag = A + (size_t)(brow + ar) * KK + ak;
    const float* Bg = W + (size_t)bk * NN + bcol + bn;

    const int kt = KK >> 5;   // K32 iterations

    // prologue: fill STAGES-1 stages
    #pragma unroll
    for (int s = 0; s < STAGES - 1; s++) {
        int k0 = s << 5;
        float* As = AsBase + s * A_STAGE;
        float* Bs = BsBase + s * B_STAGE;
        #pragma unroll
        for (int i = 0; i < 4; i++) {
            cp16(As + (ar + 32 * i) * APAD + ak, Ag + (size_t)(32 * i) * KK + k0);
            cp16(Bs + (bk + 8 * i) * BPAD + bn, Bg + (size_t)(k0 + 8 * i) * NN);
        }
        cp_commit();
    }

    int s = 0;
    for (int it = 0; it < kt; it++) {
        cp_wait<STAGES - 2>();
        __syncthreads();

        // prefetch stage it+STAGES-1
        int pf = it + STAGES - 1;
        if (pf < kt) {
            int ps = s + (STAGES - 1); if (ps >= STAGES) ps -= STAGES;
            int k0 = pf << 5;
            float* Asp = AsBase + ps * A_STAGE;
            float* Bsp = BsBase + ps * B_STAGE;
            #pragma unroll
            for (int i = 0; i < 4; i++) {
                cp16(Asp + (ar + 32 * i) * APAD + ak, Ag + (size_t)(32 * i) * KK + k0);
                cp16(Bsp + (bk + 8 * i) * BPAD + bn, Bg + (size_t)(k0 + 8 * i) * NN);
            }
        }
        cp_commit();

        const float* As = AsBase + s * A_STAGE;
        const float* Bs = BsBase + s * B_STAGE;

        #pragma unroll
        for (int ks = 0; ks < 4; ks++) {
            int kb = ks * 8;
            uint32_t af[4][4], bf[4][2];
            #pragma unroll
            for (int mi = 0; mi < 4; mi++) {
                int m0 = wm + mi * 16 + g;
                af[mi][0] = __float_as_uint(As[(m0)     * APAD + kb + t]);
                af[mi][1] = __float_as_uint(As[(m0 + 8) * APAD + kb + t]);
                af[mi][2] = __float_as_uint(As[(m0)     * APAD + kb + t + 4]);
                af[mi][3] = __float_as_uint(As[(m0 + 8) * APAD + kb + t + 4]);
            }
            #pragma unroll
            for (int ni = 0; ni < 4; ni++) {
                int n0 = wn + ni * 8 + g;
                bf[ni][0] = __float_as_uint(Bs[(kb + t)     * BPAD + n0]);
                bf[ni][1] = __float_as_uint(Bs[(kb + t + 4) * BPAD + n0]);
            }
            #pragma unroll
            for (int mi = 0; mi < 4; mi++)
                #pragma unroll
                for (int ni = 0; ni < 4; ni++)
                    mma_tf32(acc[mi][ni], af[mi][0], af[mi][1], af[mi][2], af[mi][3],
                             bf[ni][0], bf[ni][1]);
        }
        if (++s == STAGES) s = 0;
    }

    // epilogue
    #pragma unroll
    for (int mi = 0; mi < 4; mi++) {
        int r0 = brow + wm + mi * 16 + g;
        int r1 = r0 + 8;
        size_t o0, o1;
        if (EPI == EPI_PROJ) {
            #pragma unroll
            for (int h = 0; h < 2; h++) {
                int r = h ? r1 : r0;
                int b = r / TOKPI, rr = r % TOKPI;
                int wh = rr / 392; rr %= 392;
                int ww = rr / 49; int n = rr % 49;
                int ii = n / 7, jj = n % 7;
                int sr = (wh * 7 + ii + SSH) % IMG;
                int sc = (ww * 7 + jj + SSH) % IMG;
                size_t v = (size_t)(b * TOKPI + sr * IMG + sc);
                if (h) o1 = v; else o0 = v;
            }
        } else {
            o0 = (size_t)r0; o1 = (size_t)r1;
        }
        #pragma unroll
        for (int ni = 0; ni < 4; ni++) {
            int c = bcol + wn + ni * 8 + 2 * t;
            float blo = bias[c], bhi = bias[c + 1];
            float v00 = acc[mi][ni][0] + blo;
            float v01 = acc[mi][ni][1] + bhi;
            float v10 = acc[mi][ni][2] + blo;
            float v11 = acc[mi][ni][3] + bhi;
            if (EPI == EPI_GELU) {
                v00 = 0.5f * v00 * (1.f + erff(v00 * 0.70710678118654752f));
                v01 = 0.5f * v01 * (1.f + erff(v01 * 0.70710678118654752f));
                v10 = 0.5f * v10 * (1.f + erff(v10 * 0.70710678118654752f));
                v11 = 0.5f * v11 * (1.f + erff(v11 * 0.70710678118654752f));
            }
            if (EPI == EPI_PROJ || EPI == EPI_RES) {
                v00 += res[o0 * NN + c];
                v01 += res[o0 * NN + c + 1];
                v10 += res[o1 * NN + c];
                v11 += res[o1 * NN + c + 1];
            }
            float2 lo = { v00, v01 };
            float2 hi = { v10, v11 };
            *(float2*)&out[o0 * NN + c] = lo;
            *(float2*)&out[o1 * NN + c] = hi;
        }
    }
}

// ---------------- windowed attention ----------------
__device__ __forceinline__ int regid(int r) { return r < (IMG - WS) ? 0 : (r < (IMG - SSH) ? 1 : 2); }

__global__ void __launch_bounds__(128) attn_kernel(
    const float* __restrict__ qkv, const float* __restrict__ bias_table,
    float* __restrict__ o)
{
    int h  = blockIdx.x;
    int w  = blockIdx.y;
    int nw = w & 63;
    int wh = nw >> 3, ww = nw & 7;
    int tid = threadIdx.x;

    __shared__ float sq[49][33], sk[49][33], sv[49][32];
    __shared__ float ss[49][50];
    __shared__ float rsum[49];

    const float scale = 0.1767766952966369f;
    size_t base = (size_t)w * 49 * QKVC + h * HD;
    for (int idx = tid; idx < 49 * 32; idx += 128) {
        int n = idx >> 5, d = idx & 31;
        size_t rb = base + (size_t)n * QKVC + d;
        sq[n][d] = qkv[rb] * scale;
        sk[n][d] = qkv[rb + C];
        sv[n][d] = qkv[rb + 2 * C];
    }
    __syncthreads();

    for (int idx = tid; idx < 49 * 49; idx += 128) {
        int n = idx / 49, m = idx % 49;
        float dot = 0.f;
        #pragma unroll
        for (int d = 0; d < 32; d++) dot = fmaf(sq[n][d], sk[m][d], dot);
        int i1 = n / 7, j1 = n % 7, i2 = m / 7, j2 = m % 7;
        int ridx = (i1 - i2 + 6) * 13 + (j1 - j2 + 6);
        dot += bias_table[ridx * NH + h];
        int rn = regid(wh * 7 + i1) * 3 + regid(ww * 7 + j1);
        int rm = regid(wh * 7 + i2) * 3 + regid(ww * 7 + j2);
        if (rn != rm) dot -= 100.f;
        ss[n][m] = dot;
    }
    __syncthreads();

    if (tid < 49) {
        float mx = -1e30f;
        #pragma unroll 7
        for (int m = 0; m < 49; m++) mx = fmaxf(mx, ss[tid][m]);
        float sum = 0.f;
        #pragma unroll 7
        for (int m = 0; m < 49; m++) {
            float e = __expf(ss[tid][m] - mx);
            ss[tid][m] = e;
            sum += e;
        }
        rsum[tid] = 1.f / sum;
    }
    __syncthreads();

    for (int idx = tid; idx < 49 * 32; idx += 128) {
        int n = idx >> 5, d = idx & 31;
        float acc = 0.f;
        #pragma unroll 7
        for (int m = 0; m < 49; m++) acc = fmaf(ss[n][m], sv[m][d], acc);
        acc *= rsum[n];
        o[((size_t)w * 49 + n) * C + h * HD + d] = acc;
    }
}

// ---------------- launcher ----------------
extern "C" void kernel_launch(void* const* d_in, const int* in_sizes, int n_in,
                              void* d_out, int out_size)
{
    const float* x      = (const float*)d_in[0];
    const float* n1g    = (const float*)d_in[1];
    const float* n1b    = (const float*)d_in[2];
    const float* qkv_w  = (const float*)d_in[3];
    const float* qkv_b  = (const float*)d_in[4];
    const float* btab   = (const float*)d_in[5];
    const float* proj_w = (const float*)d_in[6];
    const float* proj_b = (const float*)d_in[7];
    const float* n2g    = (const float*)d_in[8];
    const float* n2b    = (const float*)d_in[9];
    const float* fc1_w  = (const float*)d_in[10];
    const float* fc1_b  = (const float*)d_in[11];
    const float* fc2_w  = (const float*)d_in[12];
    const float* fc2_b  = (const float*)d_in[13];
    float* out = (float*)d_out;

    float *hw, *qkv, *att, *x2, *fc1;
    cudaGetSymbolAddress((void**)&hw,  g_hw);
    cudaGetSymbolAddress((void**)&qkv, g_qkv);
    cudaGetSymbolAddress((void**)&att, g_att);
    cudaGetSymbolAddress((void**)&x2,  g_x2);
    cudaGetSymbolAddress((void**)&fc1, g_fc1);

    cudaFuncSetAttribute(mma_gemm<EPI_NONE>, cudaFuncAttributeMaxDynamicSharedMemorySize, SMEM_BYTES);
    cudaFuncSetAttribute(mma_gemm<EPI_GELU>, cudaFuncAttributeMaxDynamicSharedMemorySize, SMEM_BYTES);
    cudaFuncSetAttribute(mma_gemm<EPI_PROJ>, cudaFuncAttributeMaxDynamicSharedMemorySize, SMEM_BYTES);
    cudaFuncSetAttribute(mma_gemm<EPI_RES>,  cudaFuncAttributeMaxDynamicSharedMemorySize, SMEM_BYTES);

    const int gy = MROWS / 128;  // 784

    // 1. LN1 + shift + window partition
    ln_kernel<<<MROWS / 8, 256>>>(x, n1g, n1b, hw, 1);

    // 2. QKV GEMM
    mma_gemm<EPI_NONE><<<dim3(QKVC / 128, gy), 256, SMEM_BYTES>>>(hw, qkv_w, qkv_b, qkv, nullptr, QKVC, C);

    // 3. windowed attention
    attn_kernel<<<dim3(NH, BATCH * NWIN), 128>>>(qkv, btab, att);

    // 4. proj GEMM + scatter + residual
    mma_gemm<EPI_PROJ><<<dim3(C / 128, gy), 256, SMEM_BYTES>>>(att, proj_w, proj_b, x2, x, C, C);

    // 5. LN2
    ln_kernel<<<MROWS / 8, 256>>>(x2, n2g, n2b, hw, 0);

    // 6. FC1 + GELU
    mma_gemm<EPI_GELU><<<dim3(HIDDEN / 128, gy), 256, SMEM_BYTES>>>(hw, fc1_w, fc1_b, fc1, nullptr, HIDDEN, C);

    // 7. FC2 + residual
    mma_gemm<EPI_RES><<<dim3(C / 128, gy), 256, SMEM_BYTES>>>(fc1, fc2_w, fc2_b, out, x2, C, HIDDEN);
}